// round 1
// baseline (speedup 1.0000x reference)
#include <cuda_runtime.h>
#include <cuda_bf16.h>
#include <cstdint>

// Problem constants
#define Bn 4
#define Np 4096      // pixels per batch (64*64)
#define Cc 512
#define NW 640       // packed QKV output width: 64 f + 64 g + 512 v
#define NROWS (Bn*Np)

// Scratch (static device allocations -- allowed)
__device__ __nv_bfloat16 g_Xb[(size_t)NROWS * Cc];          // x in bf16
__device__ __nv_bfloat16 g_Wt[(size_t)NW * Cc];             // packed weights, [n][k] (transposed)
__device__ __nv_bfloat16 g_FG[(size_t)NROWS * 128];         // f (cols 0-63), g (cols 64-127)
__device__ __nv_bfloat16 g_Vt[(size_t)Bn * Cc * Np];        // V transposed per batch: [b][c][i]
__device__ __nv_bfloat16 g_P [(size_t)Bn * Np * Np];        // unnormalized exp(S), bf16 (128 MB)
__device__ float         g_l [NROWS];                       // row sums of P

// ---------------------------------------------------------------------------
// mma.sync m16n8k16 bf16 -> f32
// ---------------------------------------------------------------------------
__device__ __forceinline__ void mma_bf16(float c[4], const uint32_t a[4], const uint32_t b[2]) {
    asm volatile(
        "mma.sync.aligned.m16n8k16.row.col.f32.bf16.bf16.f32 "
        "{%0,%1,%2,%3}, {%4,%5,%6,%7}, {%8,%9}, {%0,%1,%2,%3};\n"
        : "+f"(c[0]), "+f"(c[1]), "+f"(c[2]), "+f"(c[3])
        : "r"(a[0]), "r"(a[1]), "r"(a[2]), "r"(a[3]),
          "r"(b[0]), "r"(b[1]));
}

#define TK 32
#define SA 40   // smem row stride in bf16 (32 + 8 pad) -> conflict-free fragment loads

// Block tile 128x128, K-tile 32, 256 threads (8 warps, 4x2 warp grid, 32x64 each).
// Both A and B are stored K-contiguous ([rows][K]) in global: identical staging.
__device__ __forceinline__ void gemm_tile(
    const __nv_bfloat16* __restrict__ Ag, int lda,
    const __nv_bfloat16* __restrict__ Bg, int ldb,
    int K, float acc[2][8][4],
    __nv_bfloat16* sA, __nv_bfloat16* sB)
{
    const int tid  = threadIdx.x;
    const int lane = tid & 31;
    const int warp = tid >> 5;
    const int wm   = warp & 3;
    const int wn   = warp >> 2;
    const int g    = lane >> 2;
    const int t4   = lane & 3;

    for (int k0 = 0; k0 < K; k0 += TK) {
        // Stage 128x32 tiles of A and B (each thread: 2 chunks of 8 bf16 per tile)
        #pragma unroll
        for (int i = 0; i < 2; i++) {
            int c   = tid + i * 256;
            int row = c >> 2;
            int col = (c & 3) << 3;
            uint4 va = *(const uint4*)(Ag + (size_t)row * lda + k0 + col);
            uint4 vb = *(const uint4*)(Bg + (size_t)row * ldb + k0 + col);
            *(uint2*)(sA + row * SA + col)     = make_uint2(va.x, va.y);
            *(uint2*)(sA + row * SA + col + 4) = make_uint2(va.z, va.w);
            *(uint2*)(sB + row * SA + col)     = make_uint2(vb.x, vb.y);
            *(uint2*)(sB + row * SA + col + 4) = make_uint2(vb.z, vb.w);
        }
        __syncthreads();

        #pragma unroll
        for (int ks = 0; ks < TK; ks += 16) {
            uint32_t a[2][4], b[8][2];
            #pragma unroll
            for (int i = 0; i < 2; i++) {
                const __nv_bfloat16* ap = sA + (wm * 32 + i * 16 + g) * SA + ks + 2 * t4;
                a[i][0] = *(const uint32_t*)(ap);
                a[i][1] = *(const uint32_t*)(ap + 8 * SA);
                a[i][2] = *(const uint32_t*)(ap + 8);
                a[i][3] = *(const uint32_t*)(ap + 8 * SA + 8);
            }
            #pragma unroll
            for (int j = 0; j < 8; j++) {
                const __nv_bfloat16* bp = sB + (wn * 64 + j * 8 + g) * SA + ks + 2 * t4;
                b[j][0] = *(const uint32_t*)(bp);
                b[j][1] = *(const uint32_t*)(bp + 8);
            }
            #pragma unroll
            for (int i = 0; i < 2; i++)
                #pragma unroll
                for (int j = 0; j < 8; j++)
                    mma_bf16(acc[i][j], a[i], b[j]);
        }
        __syncthreads();
    }
}

// ---------------------------------------------------------------------------
// Prep kernels
// ---------------------------------------------------------------------------
__global__ void convert_x(const float* __restrict__ x) {
    size_t i = (size_t)blockIdx.x * 256 + threadIdx.x;   // float4 index, exact grid
    float4 v = ((const float4*)x)[i];
    __nv_bfloat162 p0, p1;
    p0.x = __float2bfloat16(v.x); p0.y = __float2bfloat16(v.y);
    p1.x = __float2bfloat16(v.z); p1.y = __float2bfloat16(v.w);
    ((__nv_bfloat162*)g_Xb)[2 * i]     = p0;
    ((__nv_bfloat162*)g_Xb)[2 * i + 1] = p1;
}

__global__ void pack_w(const float* __restrict__ kf, const float* __restrict__ kg,
                       const float* __restrict__ kh) {
    int idx = blockIdx.x * 256 + threadIdx.x;   // 0 .. 640*512-1
    int n = idx >> 9;
    int k = idx & 511;
    float v;
    if (n < 64)       v = kf[k * 64 + n];
    else if (n < 128) v = kg[k * 64 + (n - 64)];
    else              v = kh[k * 512 + (n - 128)];
    g_Wt[idx] = __float2bfloat16(v);
}

// ---------------------------------------------------------------------------
// GEMM 1: FGV = Xb @ W   (M=16384, N=640, K=512); f/g -> g_FG, v -> g_Vt (transposed)
// ---------------------------------------------------------------------------
__global__ void gemm1_qkv() {
    __shared__ __nv_bfloat16 sA[128 * SA], sB[128 * SA];
    float acc[2][8][4];
    #pragma unroll
    for (int i = 0; i < 2; i++)
        #pragma unroll
        for (int j = 0; j < 8; j++)
            #pragma unroll
            for (int q = 0; q < 4; q++) acc[i][j][q] = 0.f;

    const int m0 = blockIdx.y * 128, n0 = blockIdx.x * 128;
    gemm_tile(g_Xb + (size_t)m0 * Cc, Cc, g_Wt + (size_t)n0 * Cc, Cc, Cc, acc, sA, sB);

    const int lane = threadIdx.x & 31, warp = threadIdx.x >> 5;
    const int wm = warp & 3, wn = warp >> 2, g = lane >> 2, t4 = lane & 3;

    #pragma unroll
    for (int i = 0; i < 2; i++) {
        #pragma unroll
        for (int h = 0; h < 2; h++) {
            int r = m0 + wm * 32 + i * 16 + g + h * 8;
            #pragma unroll
            for (int j = 0; j < 8; j++) {
                int c = n0 + wn * 64 + j * 8 + 2 * t4;
                float v0 = acc[i][j][h * 2 + 0];
                float v1 = acc[i][j][h * 2 + 1];
                if (n0 == 0) {  // f/g columns (whole block)
                    __nv_bfloat162 p;
                    p.x = __float2bfloat16(v0); p.y = __float2bfloat16(v1);
                    *(__nv_bfloat162*)&g_FG[(size_t)r * 128 + c] = p;
                } else {        // v columns -> transposed store
                    int b = r >> 12, ii = r & (Np - 1);
                    g_Vt[((size_t)b * Cc + (c - 128))     * Np + ii] = __float2bfloat16(v0);
                    g_Vt[((size_t)b * Cc + (c - 128 + 1)) * Np + ii] = __float2bfloat16(v1);
                }
            }
        }
    }
}

// ---------------------------------------------------------------------------
// GEMM 2: P = exp(F @ G^T) per batch  (4096x4096, K=64), bf16 out
// ---------------------------------------------------------------------------
__global__ void gemm2_score() {
    __shared__ __nv_bfloat16 sA[128 * SA], sB[128 * SA];
    float acc[2][8][4];
    #pragma unroll
    for (int i = 0; i < 2; i++)
        #pragma unroll
        for (int j = 0; j < 8; j++)
            #pragma unroll
            for (int q = 0; q < 4; q++) acc[i][j][q] = 0.f;

    const int n0 = blockIdx.x * 128, m0 = blockIdx.y * 128, b = blockIdx.z;
    const __nv_bfloat16* A  = g_FG + ((size_t)b * Np + m0) * 128;        // f
    const __nv_bfloat16* Bp = g_FG + ((size_t)b * Np + n0) * 128 + 64;   // g
    gemm_tile(A, 128, Bp, 128, 64, acc, sA, sB);

    __nv_bfloat16* Pb = g_P + (size_t)b * Np * Np;
    const int lane = threadIdx.x & 31, warp = threadIdx.x >> 5;
    const int wm = warp & 3, wn = warp >> 2, g = lane >> 2, t4 = lane & 3;

    #pragma unroll
    for (int i = 0; i < 2; i++) {
        #pragma unroll
        for (int h = 0; h < 2; h++) {
            int r = m0 + wm * 32 + i * 16 + g + h * 8;
            #pragma unroll
            for (int j = 0; j < 8; j++) {
                int c = n0 + wn * 64 + j * 8 + 2 * t4;
                __nv_bfloat162 p;
                p.x = __float2bfloat16(__expf(acc[i][j][h * 2 + 0]));
                p.y = __float2bfloat16(__expf(acc[i][j][h * 2 + 1]));
                *(__nv_bfloat162*)&Pb[(size_t)r * Np + c] = p;
            }
        }
    }
}

// ---------------------------------------------------------------------------
// Row sums of P: one warp per row
// ---------------------------------------------------------------------------
__global__ void rowsum() {
    int r    = blockIdx.x * 8 + (threadIdx.x >> 5);
    int lane = threadIdx.x & 31;
    const uint2* rp = (const uint2*)(g_P + (size_t)r * Np);
    float s = 0.f;
    for (int c = lane; c < Np / 4; c += 32) {
        uint2 u = rp[c];
        __nv_bfloat162 a = *(__nv_bfloat162*)&u.x;
        __nv_bfloat162 b = *(__nv_bfloat162*)&u.y;
        s += __bfloat162float(a.x) + __bfloat162float(a.y)
           + __bfloat162float(b.x) + __bfloat162float(b.y);
    }
    #pragma unroll
    for (int o = 16; o; o >>= 1) s += __shfl_down_sync(0xffffffffu, s, o);
    if (lane == 0) g_l[r] = s;
}

// ---------------------------------------------------------------------------
// GEMM 3: out = gamma * (P @ V) / l + x   (per batch 4096x512, K=4096)
// ---------------------------------------------------------------------------
__global__ void gemm3_out(const float* __restrict__ x, const float* __restrict__ gamma,
                          float* __restrict__ out) {
    __shared__ __nv_bfloat16 sA[128 * SA], sB[128 * SA];
    float acc[2][8][4];
    #pragma unroll
    for (int i = 0; i < 2; i++)
        #pragma unroll
        for (int j = 0; j < 8; j++)
            #pragma unroll
            for (int q = 0; q < 4; q++) acc[i][j][q] = 0.f;

    const int n0 = blockIdx.x * 128, m0 = blockIdx.y * 128, b = blockIdx.z;
    const __nv_bfloat16* A  = g_P  + ((size_t)b * Np + m0) * Np;
    const __nv_bfloat16* Bp = g_Vt + ((size_t)b * Cc + n0) * Np;
    gemm_tile(A, Np, Bp, Np, Np, acc, sA, sB);

    const float gam = gamma[0];
    const int lane = threadIdx.x & 31, warp = threadIdx.x >> 5;
    const int wm = warp & 3, wn = warp >> 2, g = lane >> 2, t4 = lane & 3;

    #pragma unroll
    for (int i = 0; i < 2; i++) {
        #pragma unroll
        for (int h = 0; h < 2; h++) {
            int r = b * Np + m0 + wm * 32 + i * 16 + g + h * 8;
            float inv = gam / g_l[r];
            #pragma unroll
            for (int j = 0; j < 8; j++) {
                int c = n0 + wn * 64 + j * 8 + 2 * t4;
                size_t o = (size_t)r * Cc + c;
                float2 xv = *(const float2*)(x + o);
                float2 ov;
                ov.x = acc[i][j][h * 2 + 0] * inv + xv.x;
                ov.y = acc[i][j][h * 2 + 1] * inv + xv.y;
                *(float2*)(out + o) = ov;
            }
        }
    }
}

// ---------------------------------------------------------------------------
extern "C" void kernel_launch(void* const* d_in, const int* in_sizes, int n_in,
                              void* d_out, int out_size) {
    const float* x     = (const float*)d_in[0];
    const float* kf    = (const float*)d_in[1];
    const float* kg    = (const float*)d_in[2];
    const float* kh    = (const float*)d_in[3];
    const float* gamma = (const float*)d_in[4];
    float* out = (float*)d_out;

    convert_x<<<(NROWS * Cc / 4) / 256, 256>>>(x);                 // 8192 blocks
    pack_w<<<(NW * Cc) / 256, 256>>>(kf, kg, kh);                  // 1280 blocks
    gemm1_qkv<<<dim3(NW / 128, NROWS / 128), 256>>>();             // (5,128)
    gemm2_score<<<dim3(Np / 128, Np / 128, Bn), 256>>>();          // (32,32,4)
    rowsum<<<NROWS / 8, 256>>>();                                  // 2048 blocks
    gemm3_out<<<dim3(Cc / 128, Np / 128, Bn), 256>>>(x, gamma, out);
}

// round 3
// speedup vs baseline: 1.3192x; 1.3192x over previous
#include <cuda_runtime.h>
#include <cuda_bf16.h>
#include <cstdint>

// Problem constants
#define Bn 4
#define Np 4096      // pixels per batch (64*64)
#define Cc 512
#define NW 640       // packed QKV output width: 64 f + 64 g + 512 v
#define NROWS (Bn*Np)

// Scratch (static device allocations -- allowed)
__device__ __align__(1024) __nv_bfloat16 g_Xb[(size_t)NROWS * Cc];   // x in bf16
__device__ __align__(1024) __nv_bfloat16 g_Wt[(size_t)NW * Cc];      // packed weights [n][k]
__device__ __align__(1024) __nv_bfloat16 g_FG[(size_t)NROWS * 128];  // f (0-63), g (64-127)
__device__ __align__(1024) __nv_bfloat16 g_V [(size_t)Bn * Np * Cc]; // V natural [b][i][c]
__device__ __align__(1024) __nv_bfloat16 g_Vt[(size_t)Bn * Cc * Np]; // V transposed [b][c][i]
__device__ __align__(1024) __nv_bfloat16 g_P [(size_t)Bn * Np * Np]; // exp(S) unnormalized
__device__ float g_l[NROWS];                                         // row sums of P

// ---------------------------------------------------------------------------
// mma.sync m16n8k16 bf16 -> f32  (HMMA path; tcgen05 unavailable on this target)
// ---------------------------------------------------------------------------
__device__ __forceinline__ void mma_bf16(float c[4], const uint32_t a[4], const uint32_t b[2]) {
    asm volatile(
        "mma.sync.aligned.m16n8k16.row.col.f32.bf16.bf16.f32 "
        "{%0,%1,%2,%3}, {%4,%5,%6,%7}, {%8,%9}, {%0,%1,%2,%3};\n"
        : "+f"(c[0]), "+f"(c[1]), "+f"(c[2]), "+f"(c[3])
        : "r"(a[0]), "r"(a[1]), "r"(a[2]), "r"(a[3]), "r"(b[0]), "r"(b[1]));
}

__device__ __forceinline__ uint32_t smem_to_u32(const void* p) {
    uint32_t a;
    asm("{ .reg .u64 t; cvta.to.shared.u64 t, %1; cvt.u32.u64 %0, t; }" : "=r"(a) : "l"(p));
    return a;
}
__device__ __forceinline__ void cp16(uint32_t dst, const void* src) {
    asm volatile("cp.async.cg.shared.global [%0], [%1], 16;\n" :: "r"(dst), "l"(src));
}
#define CP_COMMIT() asm volatile("cp.async.commit_group;\n" ::: "memory")
#define CP_WAIT(n)  asm volatile("cp.async.wait_group %0;\n" :: "n"(n) : "memory")

#define TK  32
#define SA  40                      // smem row stride in bf16 (conflict-free frags)
#define STG (128 * SA)              // elements per staged tile (A or B)
#define NS  3                       // pipeline stages
#define GEMM_SMEM (NS * 2 * STG * 2)  // bytes = 61440

// Block tile 128x128, K-tile 32, 256 threads (8 warps, 4x2 grid, 32x64 each).
// cp.async 3-stage pipeline; both operands K-contiguous ([rows][K]) in global.
__device__ __forceinline__ void gemm_tile(
    const __nv_bfloat16* __restrict__ Ag, int lda,
    const __nv_bfloat16* __restrict__ Bg, int ldb,
    int K, float acc[2][8][4], __nv_bfloat16* smem)
{
    const int tid = threadIdx.x, lane = tid & 31, warp = tid >> 5;
    const int wm = warp & 3, wn = warp >> 2, g = lane >> 2, t4 = lane & 3;
    const uint32_t sbase = smem_to_u32(smem);
    const int r0 = tid >> 2;            // 0..63 (second chunk: r0+64)
    const int c0 = (tid & 3) << 3;      // 0,8,16,24
    const int nk = K / TK;

    auto issue = [&](int i) {
        const int s = i % NS;
        const uint32_t sa = sbase + (uint32_t)(s * 2 * STG) * 2;
        const uint32_t sb = sa + STG * 2;
        const int k0 = i * TK;
        cp16(sa + (r0 * SA + c0) * 2,        Ag + (size_t)r0 * lda + k0 + c0);
        cp16(sa + ((r0 + 64) * SA + c0) * 2, Ag + (size_t)(r0 + 64) * lda + k0 + c0);
        cp16(sb + (r0 * SA + c0) * 2,        Bg + (size_t)r0 * ldb + k0 + c0);
        cp16(sb + ((r0 + 64) * SA + c0) * 2, Bg + (size_t)(r0 + 64) * ldb + k0 + c0);
        CP_COMMIT();
    };

    // Prologue: fill up to NS-1 stages
    if (nk > 0) issue(0);
    if (nk > 1) issue(1);

    for (int i = 0; i < nk; i++) {
        if (i == nk - 1) CP_WAIT(0); else CP_WAIT(1);
        __syncthreads();
        if (i + NS - 1 < nk) issue(i + NS - 1);

        const __nv_bfloat16* cA = smem + (i % NS) * (2 * STG);
        const __nv_bfloat16* cB = cA + STG;
        #pragma unroll
        for (int ks = 0; ks < TK; ks += 16) {
            uint32_t a[2][4], b[8][2];
            #pragma unroll
            for (int ii = 0; ii < 2; ii++) {
                const __nv_bfloat16* ap = cA + (wm * 32 + ii * 16 + g) * SA + ks + 2 * t4;
                a[ii][0] = *(const uint32_t*)(ap);
                a[ii][1] = *(const uint32_t*)(ap + 8 * SA);
                a[ii][2] = *(const uint32_t*)(ap + 8);
                a[ii][3] = *(const uint32_t*)(ap + 8 * SA + 8);
            }
            #pragma unroll
            for (int j = 0; j < 8; j++) {
                const __nv_bfloat16* bp = cB + (wn * 64 + j * 8 + g) * SA + ks + 2 * t4;
                b[j][0] = *(const uint32_t*)(bp);
                b[j][1] = *(const uint32_t*)(bp + 8);
            }
            #pragma unroll
            for (int ii = 0; ii < 2; ii++)
                #pragma unroll
                for (int j = 0; j < 8; j++)
                    mma_bf16(acc[ii][j], a[ii], b[j]);
        }
        __syncthreads();   // protect buffer (i%NS) before it is re-filled
    }
}

// ---------------------------------------------------------------------------
// Prep kernels
// ---------------------------------------------------------------------------
__global__ void convert_x(const float* __restrict__ x) {
    size_t i = (size_t)blockIdx.x * 256 + threadIdx.x;
    float4 v = ((const float4*)x)[i];
    __nv_bfloat162 p0, p1;
    p0.x = __float2bfloat16(v.x); p0.y = __float2bfloat16(v.y);
    p1.x = __float2bfloat16(v.z); p1.y = __float2bfloat16(v.w);
    ((__nv_bfloat162*)g_Xb)[2 * i]     = p0;
    ((__nv_bfloat162*)g_Xb)[2 * i + 1] = p1;
}

__global__ void pack_w(const float* __restrict__ kf, const float* __restrict__ kg,
                       const float* __restrict__ kh) {
    int idx = blockIdx.x * 256 + threadIdx.x;
    int n = idx >> 9, k = idx & 511;
    float v;
    if (n < 64)       v = kf[k * 64 + n];
    else if (n < 128) v = kg[k * 64 + (n - 64)];
    else              v = kh[k * 512 + (n - 128)];
    g_Wt[idx] = __float2bfloat16(v);
}

__global__ void zero_l() {
    int i = blockIdx.x * 1024 + threadIdx.x;
    if (i < NROWS) g_l[i] = 0.f;
}

// ---------------------------------------------------------------------------
// GEMM 1: [f|g|v] = Xb @ W ; f/g -> g_FG, v -> g_V (natural, coalesced)
// ---------------------------------------------------------------------------
__global__ void __launch_bounds__(256, 2) gemm1_qkv() {
    extern __shared__ __nv_bfloat16 smem[];
    float acc[2][8][4];
    #pragma unroll
    for (int i = 0; i < 2; i++)
        #pragma unroll
        for (int j = 0; j < 8; j++)
            #pragma unroll
            for (int q = 0; q < 4; q++) acc[i][j][q] = 0.f;

    const int m0 = blockIdx.y * 128, n0 = blockIdx.x * 128;
    gemm_tile(g_Xb + (size_t)m0 * Cc, Cc, g_Wt + (size_t)n0 * Cc, Cc, Cc, acc, smem);

    const int lane = threadIdx.x & 31, warp = threadIdx.x >> 5;
    const int wm = warp & 3, wn = warp >> 2, g = lane >> 2, t4 = lane & 3;
    #pragma unroll
    for (int i = 0; i < 2; i++) {
        #pragma unroll
        for (int h = 0; h < 2; h++) {
            int r = m0 + wm * 32 + i * 16 + g + h * 8;
            #pragma unroll
            for (int j = 0; j < 8; j++) {
                int c = n0 + wn * 64 + j * 8 + 2 * t4;
                __nv_bfloat162 p;
                p.x = __float2bfloat16(acc[i][j][h * 2 + 0]);
                p.y = __float2bfloat16(acc[i][j][h * 2 + 1]);
                if (n0 == 0) *(__nv_bfloat162*)&g_FG[(size_t)r * 128 + c] = p;
                else         *(__nv_bfloat162*)&g_V [(size_t)r * Cc + (c - 128)] = p;
            }
        }
    }
}

// ---------------------------------------------------------------------------
// Transpose V [b][i][c] -> Vt [b][c][i] (smem tiled, coalesced both sides)
// ---------------------------------------------------------------------------
__global__ void vtrans() {
    __shared__ __nv_bfloat16 t[64 * 72];
    const int bb = blockIdx.z, it = blockIdx.x, ct = blockIdx.y;
    const __nv_bfloat16* src = g_V + ((size_t)bb * Np + it * 64) * Cc + ct * 64;
    #pragma unroll
    for (int k = 0; k < 2; k++) {
        int u = threadIdx.x + k * 256;
        int row = u >> 3, c8 = (u & 7) * 8;
        *(uint4*)(t + row * 72 + c8) = *(const uint4*)(src + (size_t)row * Cc + c8);
    }
    __syncthreads();
    __nv_bfloat16* dst = g_Vt + ((size_t)bb * Cc + ct * 64) * Np + it * 64;
    #pragma unroll
    for (int k = 0; k < 2; k++) {
        int u = threadIdx.x + k * 256;
        int orow = u >> 3, i8 = (u & 7) * 8;
        __nv_bfloat16 tmp[8];
        #pragma unroll
        for (int q = 0; q < 8; q++) tmp[q] = t[(i8 + q) * 72 + orow];
        *(uint4*)(dst + (size_t)orow * Np + i8) = *(uint4*)tmp;
    }
}

// ---------------------------------------------------------------------------
// GEMM 2: P = exp(F @ G^T) per batch, + fused row-sum atomics
// ---------------------------------------------------------------------------
__global__ void __launch_bounds__(256, 2) gemm2_score() {
    extern __shared__ __nv_bfloat16 smem[];
    float acc[2][8][4];
    #pragma unroll
    for (int i = 0; i < 2; i++)
        #pragma unroll
        for (int j = 0; j < 8; j++)
            #pragma unroll
            for (int q = 0; q < 4; q++) acc[i][j][q] = 0.f;

    const int n0 = blockIdx.x * 128, m0 = blockIdx.y * 128, bb = blockIdx.z;
    const __nv_bfloat16* A  = g_FG + ((size_t)bb * Np + m0) * 128;       // f
    const __nv_bfloat16* Bp = g_FG + ((size_t)bb * Np + n0) * 128 + 64;  // g
    gemm_tile(A, 128, Bp, 128, 64, acc, smem);

    __nv_bfloat16* Pb = g_P + (size_t)bb * Np * Np;
    const int lane = threadIdx.x & 31, warp = threadIdx.x >> 5;
    const int wm = warp & 3, wn = warp >> 2, g = lane >> 2, t4 = lane & 3;

    float rs[2][2] = {{0.f, 0.f}, {0.f, 0.f}};
    #pragma unroll
    for (int i = 0; i < 2; i++) {
        #pragma unroll
        for (int h = 0; h < 2; h++) {
            int r = m0 + wm * 32 + i * 16 + g + h * 8;
            #pragma unroll
            for (int j = 0; j < 8; j++) {
                int c = n0 + wn * 64 + j * 8 + 2 * t4;
                __nv_bfloat162 p;
                p.x = __float2bfloat16(__expf(acc[i][j][h * 2 + 0]));
                p.y = __float2bfloat16(__expf(acc[i][j][h * 2 + 1]));
                *(__nv_bfloat162*)&Pb[(size_t)r * Np + c] = p;
                rs[i][h] += __bfloat162float(p.x) + __bfloat162float(p.y);
            }
        }
    }
    // quad-reduce (t4 lanes share row) then atomicAdd
    #pragma unroll
    for (int i = 0; i < 2; i++) {
        #pragma unroll
        for (int h = 0; h < 2; h++) {
            float v = rs[i][h];
            v += __shfl_down_sync(0xffffffffu, v, 2, 4);
            v += __shfl_down_sync(0xffffffffu, v, 1, 4);
            if (t4 == 0) {
                int r = m0 + wm * 32 + i * 16 + g + h * 8;
                atomicAdd(&g_l[(size_t)bb * Np + r], v);
            }
        }
    }
}

// ---------------------------------------------------------------------------
// GEMM 3: out = gamma * (P @ Vt^T) / l + x   (per batch 4096x512, K=4096)
// ---------------------------------------------------------------------------
__global__ void __launch_bounds__(256, 2) gemm3_out(
    const float* __restrict__ x, const float* __restrict__ gamma,
    float* __restrict__ out)
{
    extern __shared__ __nv_bfloat16 smem[];
    float acc[2][8][4];
    #pragma unroll
    for (int i = 0; i < 2; i++)
        #pragma unroll
        for (int j = 0; j < 8; j++)
            #pragma unroll
            for (int q = 0; q < 4; q++) acc[i][j][q] = 0.f;

    const int n0 = blockIdx.x * 128, m0 = blockIdx.y * 128, bb = blockIdx.z;
    const __nv_bfloat16* A  = g_P  + ((size_t)bb * Np + m0) * Np;
    const __nv_bfloat16* Bp = g_Vt + ((size_t)bb * Cc + n0) * Np;
    gemm_tile(A, Np, Bp, Np, Np, acc, smem);

    const float gam = gamma[0];
    const int lane = threadIdx.x & 31, warp = threadIdx.x >> 5;
    const int wm = warp & 3, wn = warp >> 2, g = lane >> 2, t4 = lane & 3;

    #pragma unroll
    for (int i = 0; i < 2; i++) {
        #pragma unroll
        for (int h = 0; h < 2; h++) {
            int r = bb * Np + m0 + wm * 32 + i * 16 + g + h * 8;
            float inv = gam / g_l[r];
            #pragma unroll
            for (int j = 0; j < 8; j++) {
                int c = n0 + wn * 64 + j * 8 + 2 * t4;
                size_t o = (size_t)r * Cc + c;
                float2 xv = *(const float2*)(x + o);
                float2 ov;
                ov.x = acc[i][j][h * 2 + 0] * inv + xv.x;
                ov.y = acc[i][j][h * 2 + 1] * inv + xv.y;
                *(float2*)(out + o) = ov;
            }
        }
    }
}

// ===========================================================================
extern "C" void kernel_launch(void* const* d_in, const int* in_sizes, int n_in,
                              void* d_out, int out_size) {
    const float* x     = (const float*)d_in[0];
    const float* kf    = (const float*)d_in[1];
    const float* kg    = (const float*)d_in[2];
    const float* kh    = (const float*)d_in[3];
    const float* gamma = (const float*)d_in[4];
    float* out = (float*)d_out;

    static bool attr_done = false;
    if (!attr_done) {
        cudaFuncSetAttribute(gemm1_qkv,  cudaFuncAttributeMaxDynamicSharedMemorySize, GEMM_SMEM);
        cudaFuncSetAttribute(gemm2_score, cudaFuncAttributeMaxDynamicSharedMemorySize, GEMM_SMEM);
        cudaFuncSetAttribute(gemm3_out,  cudaFuncAttributeMaxDynamicSharedMemorySize, GEMM_SMEM);
        attr_done = true;
    }

    convert_x<<<(NROWS * Cc / 4) / 256, 256>>>(x);
    pack_w<<<(NW * Cc) / 256, 256>>>(kf, kg, kh);
    zero_l<<<16, 1024>>>();
    gemm1_qkv<<<dim3(NW / 128, NROWS / 128), 256, GEMM_SMEM>>>();
    vtrans<<<dim3(64, 8, 4), 256>>>();
    gemm2_score<<<dim3(Np / 128, Np / 128, Bn), 256, GEMM_SMEM>>>();
    gemm3_out<<<dim3(Cc / 128, Np / 128, Bn), 256, GEMM_SMEM>>>(x, gamma, out);
}

// round 4
// speedup vs baseline: 1.4423x; 1.0933x over previous
#include <cuda_runtime.h>
#include <cuda_bf16.h>
#include <cstdint>

// Problem constants
#define Bn 4
#define Np 4096      // pixels per batch (64*64)
#define Cc 512
#define NW 640       // packed QKV output width: 64 f + 64 g + 512 v
#define NROWS (Bn*Np)

// Scratch (static device allocations -- allowed)
__device__ __align__(1024) __nv_bfloat16 g_Xb[(size_t)NROWS * Cc];   // x in bf16
__device__ __align__(1024) __nv_bfloat16 g_Wt[(size_t)NW * Cc];      // packed weights [n][k]
__device__ __align__(1024) __nv_bfloat16 g_FG[(size_t)NROWS * 128];  // f (0-63), g (64-127)
__device__ __align__(1024) __nv_bfloat16 g_V [(size_t)Bn * Np * Cc]; // V natural [b][i][c]
__device__ __align__(1024) __nv_bfloat16 g_Vt[(size_t)Bn * Cc * Np]; // V transposed [b][c][i]
__device__ __align__(1024) __nv_bfloat16 g_P [(size_t)Bn * Np * Np]; // exp(S) unnormalized
__device__ float g_l[NROWS];                                         // row sums of P

// ---------------------------------------------------------------------------
// mma.sync m16n8k16 bf16 -> f32  (HMMA path; tcgen05 unavailable on sm_100 target)
// ---------------------------------------------------------------------------
__device__ __forceinline__ void mma_bf16(float c[4], const uint32_t a[4],
                                         uint32_t b0, uint32_t b1) {
    asm volatile(
        "mma.sync.aligned.m16n8k16.row.col.f32.bf16.bf16.f32 "
        "{%0,%1,%2,%3}, {%4,%5,%6,%7}, {%8,%9}, {%0,%1,%2,%3};\n"
        : "+f"(c[0]), "+f"(c[1]), "+f"(c[2]), "+f"(c[3])
        : "r"(a[0]), "r"(a[1]), "r"(a[2]), "r"(a[3]), "r"(b0), "r"(b1));
}
__device__ __forceinline__ void ldsm4(uint32_t& r0, uint32_t& r1, uint32_t& r2,
                                      uint32_t& r3, uint32_t addr) {
    asm volatile("ldmatrix.sync.aligned.m8n8.x4.shared.b16 {%0,%1,%2,%3}, [%4];"
                 : "=r"(r0), "=r"(r1), "=r"(r2), "=r"(r3) : "r"(addr));
}
__device__ __forceinline__ uint32_t smem_to_u32(const void* p) {
    uint32_t a;
    asm("{ .reg .u64 t; cvta.to.shared.u64 t, %1; cvt.u32.u64 %0, t; }" : "=r"(a) : "l"(p));
    return a;
}
__device__ __forceinline__ void cp16(uint32_t dst, const void* src) {
    asm volatile("cp.async.cg.shared.global [%0], [%1], 16;\n" :: "r"(dst), "l"(src));
}
#define CP_COMMIT() asm volatile("cp.async.commit_group;\n" ::: "memory")
#define CP_WAIT(n)  asm volatile("cp.async.wait_group %0;\n" :: "n"(n) : "memory")

#define TK  32
#define SA  40                        // smem row stride in bf16 (conflict-free)
#define STG (128 * SA)                // elements per staged tile (A or B)
#define NS  4                         // pipeline stages
#define GEMM_SMEM (NS * 2 * STG * 2)  // bytes = 81920

// Block tile 128x128, K-tile 32, 256 threads (8 warps, 4x2 grid, 32x64 each).
// cp.async 4-stage pipeline + ldmatrix fragment loads.
__device__ __forceinline__ void gemm_tile(
    const __nv_bfloat16* __restrict__ Ag, int lda,
    const __nv_bfloat16* __restrict__ Bg, int ldb,
    int K, float acc[2][8][4], __nv_bfloat16* smem)
{
    const int tid = threadIdx.x, lane = tid & 31, warp = tid >> 5;
    const int wm = warp & 3, wn = warp >> 2;
    const uint32_t sbase = smem_to_u32(smem);
    const int r0 = tid >> 2;            // staging row 0..63 (+64 for 2nd chunk)
    const int c0 = (tid & 3) << 3;      // staging col {0,8,16,24}
    const int nk = K / TK;

    // Per-lane ldmatrix base byte-offsets within a stage buffer.
    // A (ii tile): row = wm*32 + ii*16 + ((l>>3)&1)*8 + (l&7), col = (l>>4)*8 (+ks)
    // B (jp pair): row = wn*64 + jp*16 + (l>>4)*8 + (l&7),    col = ((l>>3)&1)*8 (+ks)
    const uint32_t offA0 = (uint32_t)((wm * 32 + ((lane >> 3) & 1) * 8 + (lane & 7)) * SA
                                      + (lane >> 4) * 8) * 2;
    const uint32_t offA1 = offA0 + 16 * SA * 2;
    const uint32_t offB0 = (uint32_t)(STG + (wn * 64 + (lane >> 4) * 8 + (lane & 7)) * SA
                                      + ((lane >> 3) & 1) * 8) * 2;

    auto issue = [&](int i) {
        const int s = i % NS;
        const uint32_t sa = sbase + (uint32_t)(s * 2 * STG) * 2;
        const uint32_t sb = sa + STG * 2;
        const int k0 = i * TK;
        cp16(sa + (r0 * SA + c0) * 2,        Ag + (size_t)r0 * lda + k0 + c0);
        cp16(sa + ((r0 + 64) * SA + c0) * 2, Ag + (size_t)(r0 + 64) * lda + k0 + c0);
        cp16(sb + (r0 * SA + c0) * 2,        Bg + (size_t)r0 * ldb + k0 + c0);
        cp16(sb + ((r0 + 64) * SA + c0) * 2, Bg + (size_t)(r0 + 64) * ldb + k0 + c0);
        CP_COMMIT();
    };

    // Prologue: fill up to NS-1 stages
    #pragma unroll
    for (int p = 0; p < NS - 1; p++)
        if (p < nk) issue(p);

    for (int i = 0; i < nk; i++) {
        const int rem = nk - 1 - i;     // groups issued beyond i = min(2, rem)
        if (rem >= 2)      CP_WAIT(2);
        else if (rem == 1) CP_WAIT(1);
        else               CP_WAIT(0);
        __syncthreads();
        if (i + NS - 1 < nk) issue(i + NS - 1);

        const uint32_t bb = sbase + (uint32_t)((i % NS) * 2 * STG) * 2;
        #pragma unroll
        for (int ks = 0; ks < 2; ks++) {            // two k16 halves of the K-tile
            const uint32_t kofs = ks * 32;          // 16 bf16 = 32 bytes
            uint32_t a[2][4], b4[4][4];
            ldsm4(a[0][0], a[0][1], a[0][2], a[0][3], bb + offA0 + kofs);
            ldsm4(a[1][0], a[1][1], a[1][2], a[1][3], bb + offA1 + kofs);
            #pragma unroll
            for (int jp = 0; jp < 4; jp++)
                ldsm4(b4[jp][0], b4[jp][1], b4[jp][2], b4[jp][3],
                      bb + offB0 + (uint32_t)(jp * 16 * SA * 2) + kofs);
            #pragma unroll
            for (int ii = 0; ii < 2; ii++)
                #pragma unroll
                for (int jp = 0; jp < 4; jp++) {
                    mma_bf16(acc[ii][2 * jp],     a[ii], b4[jp][0], b4[jp][1]);
                    mma_bf16(acc[ii][2 * jp + 1], a[ii], b4[jp][2], b4[jp][3]);
                }
        }
        __syncthreads();   // protect buffer before it is re-filled
    }
}

// ---------------------------------------------------------------------------
// Prep kernels
// ---------------------------------------------------------------------------
__global__ void convert_x(const float* __restrict__ x) {
    size_t i = (size_t)blockIdx.x * 256 + threadIdx.x;
    float4 v = ((const float4*)x)[i];
    __nv_bfloat162 p0, p1;
    p0.x = __float2bfloat16(v.x); p0.y = __float2bfloat16(v.y);
    p1.x = __float2bfloat16(v.z); p1.y = __float2bfloat16(v.w);
    ((__nv_bfloat162*)g_Xb)[2 * i]     = p0;
    ((__nv_bfloat162*)g_Xb)[2 * i + 1] = p1;
}

__global__ void pack_w(const float* __restrict__ kf, const float* __restrict__ kg,
                       const float* __restrict__ kh) {
    int idx = blockIdx.x * 256 + threadIdx.x;
    int n = idx >> 9, k = idx & 511;
    float v;
    if (n < 64)       v = kf[k * 64 + n];
    else if (n < 128) v = kg[k * 64 + (n - 64)];
    else              v = kh[k * 512 + (n - 128)];
    g_Wt[idx] = __float2bfloat16(v);
}

__global__ void zero_l() {
    int i = blockIdx.x * 1024 + threadIdx.x;
    if (i < NROWS) g_l[i] = 0.f;
}

// ---------------------------------------------------------------------------
// GEMM 1: [f|g|v] = Xb @ W ; f/g -> g_FG, v -> g_V (natural, coalesced)
// ---------------------------------------------------------------------------
__global__ void __launch_bounds__(256, 2) gemm1_qkv() {
    extern __shared__ __nv_bfloat16 smem[];
    float acc[2][8][4];
    #pragma unroll
    for (int i = 0; i < 2; i++)
        #pragma unroll
        for (int j = 0; j < 8; j++)
            #pragma unroll
            for (int q = 0; q < 4; q++) acc[i][j][q] = 0.f;

    const int m0 = blockIdx.y * 128, n0 = blockIdx.x * 128;
    gemm_tile(g_Xb + (size_t)m0 * Cc, Cc, g_Wt + (size_t)n0 * Cc, Cc, Cc, acc, smem);

    const int lane = threadIdx.x & 31, warp = threadIdx.x >> 5;
    const int wm = warp & 3, wn = warp >> 2, g = lane >> 2, t4 = lane & 3;
    #pragma unroll
    for (int i = 0; i < 2; i++) {
        #pragma unroll
        for (int h = 0; h < 2; h++) {
            int r = m0 + wm * 32 + i * 16 + g + h * 8;
            #pragma unroll
            for (int j = 0; j < 8; j++) {
                int c = n0 + wn * 64 + j * 8 + 2 * t4;
                __nv_bfloat162 p;
                p.x = __float2bfloat16(acc[i][j][h * 2 + 0]);
                p.y = __float2bfloat16(acc[i][j][h * 2 + 1]);
                if (n0 == 0) *(__nv_bfloat162*)&g_FG[(size_t)r * 128 + c] = p;
                else         *(__nv_bfloat162*)&g_V [(size_t)r * Cc + (c - 128)] = p;
            }
        }
    }
}

// ---------------------------------------------------------------------------
// Transpose V [b][i][c] -> Vt [b][c][i] (smem tiled, coalesced both sides)
// ---------------------------------------------------------------------------
__global__ void vtrans() {
    __shared__ __nv_bfloat16 t[64 * 72];
    const int bb = blockIdx.z, it = blockIdx.x, ct = blockIdx.y;
    const __nv_bfloat16* src = g_V + ((size_t)bb * Np + it * 64) * Cc + ct * 64;
    #pragma unroll
    for (int k = 0; k < 2; k++) {
        int u = threadIdx.x + k * 256;
        int row = u >> 3, c8 = (u & 7) * 8;
        *(uint4*)(t + row * 72 + c8) = *(const uint4*)(src + (size_t)row * Cc + c8);
    }
    __syncthreads();
    __nv_bfloat16* dst = g_Vt + ((size_t)bb * Cc + ct * 64) * Np + it * 64;
    #pragma unroll
    for (int k = 0; k < 2; k++) {
        int u = threadIdx.x + k * 256;
        int orow = u >> 3, i8 = (u & 7) * 8;
        __nv_bfloat16 tmp[8];
        #pragma unroll
        for (int q = 0; q < 8; q++) tmp[q] = t[(i8 + q) * 72 + orow];
        *(uint4*)(dst + (size_t)orow * Np + i8) = *(uint4*)tmp;
    }
}

// ---------------------------------------------------------------------------
// GEMM 2: P = exp(F @ G^T) per batch, + fused row-sum atomics
// ---------------------------------------------------------------------------
__global__ void __launch_bounds__(256, 2) gemm2_score() {
    extern __shared__ __nv_bfloat16 smem[];
    float acc[2][8][4];
    #pragma unroll
    for (int i = 0; i < 2; i++)
        #pragma unroll
        for (int j = 0; j < 8; j++)
            #pragma unroll
            for (int q = 0; q < 4; q++) acc[i][j][q] = 0.f;

    const int n0 = blockIdx.x * 128, m0 = blockIdx.y * 128, bb = blockIdx.z;
    const __nv_bfloat16* A  = g_FG + ((size_t)bb * Np + m0) * 128;       // f
    const __nv_bfloat16* Bp = g_FG + ((size_t)bb * Np + n0) * 128 + 64;  // g
    gemm_tile(A, 128, Bp, 128, 64, acc, smem);

    __nv_bfloat16* Pb = g_P + (size_t)bb * Np * Np;
    const int lane = threadIdx.x & 31, warp = threadIdx.x >> 5;
    const int wm = warp & 3, wn = warp >> 2, g = lane >> 2, t4 = lane & 3;

    float rs[2][2] = {{0.f, 0.f}, {0.f, 0.f}};
    #pragma unroll
    for (int i = 0; i < 2; i++) {
        #pragma unroll
        for (int h = 0; h < 2; h++) {
            int r = m0 + wm * 32 + i * 16 + g + h * 8;
            #pragma unroll
            for (int j = 0; j < 8; j++) {
                int c = n0 + wn * 64 + j * 8 + 2 * t4;
                __nv_bfloat162 p;
                p.x = __float2bfloat16(__expf(acc[i][j][h * 2 + 0]));
                p.y = __float2bfloat16(__expf(acc[i][j][h * 2 + 1]));
                *(__nv_bfloat162*)&Pb[(size_t)r * Np + c] = p;
                rs[i][h] += __bfloat162float(p.x) + __bfloat162float(p.y);
            }
        }
    }
    #pragma unroll
    for (int i = 0; i < 2; i++) {
        #pragma unroll
        for (int h = 0; h < 2; h++) {
            float v = rs[i][h];
            v += __shfl_down_sync(0xffffffffu, v, 2, 4);
            v += __shfl_down_sync(0xffffffffu, v, 1, 4);
            if (t4 == 0) {
                int r = m0 + wm * 32 + i * 16 + g + h * 8;
                atomicAdd(&g_l[(size_t)bb * Np + r], v);
            }
        }
    }
}

// ---------------------------------------------------------------------------
// GEMM 3: out = gamma * (P @ Vt^T) / l + x   (per batch 4096x512, K=4096)
// ---------------------------------------------------------------------------
__global__ void __launch_bounds__(256, 2) gemm3_out(
    const float* __restrict__ x, const float* __restrict__ gamma,
    float* __restrict__ out)
{
    extern __shared__ __nv_bfloat16 smem[];
    float acc[2][8][4];
    #pragma unroll
    for (int i = 0; i < 2; i++)
        #pragma unroll
        for (int j = 0; j < 8; j++)
            #pragma unroll
            for (int q = 0; q < 4; q++) acc[i][j][q] = 0.f;

    const int n0 = blockIdx.x * 128, m0 = blockIdx.y * 128, bb = blockIdx.z;
    const __nv_bfloat16* A  = g_P  + ((size_t)bb * Np + m0) * Np;
    const __nv_bfloat16* Bp = g_Vt + ((size_t)bb * Cc + n0) * Np;
    gemm_tile(A, Np, Bp, Np, Np, acc, smem);

    const float gam = gamma[0];
    const int lane = threadIdx.x & 31, warp = threadIdx.x >> 5;
    const int wm = warp & 3, wn = warp >> 2, g = lane >> 2, t4 = lane & 3;

    #pragma unroll
    for (int i = 0; i < 2; i++) {
        #pragma unroll
        for (int h = 0; h < 2; h++) {
            int r = bb * Np + m0 + wm * 32 + i * 16 + g + h * 8;
            float inv = gam / g_l[r];
            #pragma unroll
            for (int j = 0; j < 8; j++) {
                int c = n0 + wn * 64 + j * 8 + 2 * t4;
                size_t o = (size_t)r * Cc + c;
                float2 xv = *(const float2*)(x + o);
                float2 ov;
                ov.x = acc[i][j][h * 2 + 0] * inv + xv.x;
                ov.y = acc[i][j][h * 2 + 1] * inv + xv.y;
                *(float2*)(out + o) = ov;
            }
        }
    }
}

// ===========================================================================
extern "C" void kernel_launch(void* const* d_in, const int* in_sizes, int n_in,
                              void* d_out, int out_size) {
    const float* x     = (const float*)d_in[0];
    const float* kf    = (const float*)d_in[1];
    const float* kg    = (const float*)d_in[2];
    const float* kh    = (const float*)d_in[3];
    const float* gamma = (const float*)d_in[4];
    float* out = (float*)d_out;

    static bool attr_done = false;
    if (!attr_done) {
        cudaFuncSetAttribute(gemm1_qkv,   cudaFuncAttributeMaxDynamicSharedMemorySize, GEMM_SMEM);
        cudaFuncSetAttribute(gemm2_score, cudaFuncAttributeMaxDynamicSharedMemorySize, GEMM_SMEM);
        cudaFuncSetAttribute(gemm3_out,   cudaFuncAttributeMaxDynamicSharedMemorySize, GEMM_SMEM);
        attr_done = true;
    }

    convert_x<<<(NROWS * Cc / 4) / 256, 256>>>(x);
    pack_w<<<(NW * Cc) / 256, 256>>>(kf, kg, kh);
    zero_l<<<16, 1024>>>();
    gemm1_qkv<<<dim3(NW / 128, NROWS / 128), 256, GEMM_SMEM>>>();
    vtrans<<<dim3(64, 8, 4), 256>>>();
    gemm2_score<<<dim3(Np / 128, Np / 128, Bn), 256, GEMM_SMEM>>>();
    gemm3_out<<<dim3(Cc / 128, Np / 128, Bn), 256, GEMM_SMEM>>>(x, gamma, out);
}

// round 5
// speedup vs baseline: 1.5527x; 1.0765x over previous
#include <cuda_runtime.h>
#include <cuda_bf16.h>
#include <cstdint>

// Problem constants
#define Bn 4
#define Np 4096      // pixels per batch (64*64)
#define Cc 512
#define NW 640       // packed QKV output width: 64 f + 64 g + 512 v
#define NROWS (Bn*Np)

// Scratch (static device allocations -- allowed)
__device__ __align__(1024) __nv_bfloat16 g_Xb[(size_t)NROWS * Cc];   // x in bf16
__device__ __align__(1024) __nv_bfloat16 g_Wt[(size_t)NW * Cc];      // packed weights [n][k]
__device__ __align__(1024) __nv_bfloat16 g_FG[(size_t)NROWS * 128];  // f (0-63), g (64-127)
__device__ __align__(1024) __nv_bfloat16 g_V [(size_t)Bn * Np * Cc]; // V natural [b][i][c]
__device__ __align__(1024) __nv_bfloat16 g_Vt[(size_t)Bn * Cc * Np]; // V transposed [b][c][i]
__device__ __align__(1024) __nv_bfloat16 g_P [(size_t)Bn * Np * Np]; // exp(S) unnormalized
__device__ float g_l[NROWS];                                         // row sums of P

// ---------------------------------------------------------------------------
// mma.sync m16n8k16 bf16 -> f32  (HMMA path; tcgen05 unavailable on sm_100 target)
// ---------------------------------------------------------------------------
__device__ __forceinline__ void mma_bf16(float c[4], const uint32_t a[4],
                                         uint32_t b0, uint32_t b1) {
    asm volatile(
        "mma.sync.aligned.m16n8k16.row.col.f32.bf16.bf16.f32 "
        "{%0,%1,%2,%3}, {%4,%5,%6,%7}, {%8,%9}, {%0,%1,%2,%3};\n"
        : "+f"(c[0]), "+f"(c[1]), "+f"(c[2]), "+f"(c[3])
        : "r"(a[0]), "r"(a[1]), "r"(a[2]), "r"(a[3]), "r"(b0), "r"(b1));
}
__device__ __forceinline__ void ldsm4(uint32_t& r0, uint32_t& r1, uint32_t& r2,
                                      uint32_t& r3, uint32_t addr) {
    asm volatile("ldmatrix.sync.aligned.m8n8.x4.shared.b16 {%0,%1,%2,%3}, [%4];"
                 : "=r"(r0), "=r"(r1), "=r"(r2), "=r"(r3) : "r"(addr));
}
__device__ __forceinline__ uint32_t smem_to_u32(const void* p) {
    uint32_t a;
    asm("{ .reg .u64 t; cvta.to.shared.u64 t, %1; cvt.u32.u64 %0, t; }" : "=r"(a) : "l"(p));
    return a;
}
__device__ __forceinline__ void cp16(uint32_t dst, const void* src) {
    asm volatile("cp.async.cg.shared.global [%0], [%1], 16;\n" :: "r"(dst), "l"(src));
}
#define CP_COMMIT() asm volatile("cp.async.commit_group;\n" ::: "memory")
#define CP_WAIT(n)  asm volatile("cp.async.wait_group %0;\n" :: "n"(n) : "memory")

#define TK  64
#define SA  72                        // smem row stride in bf16 (conflict-free)
#define STG (128 * SA)                // elements per staged tile (A or B)
#define NS  3                         // pipeline stages
#define GEMM_SMEM (NS * 2 * STG * 2)  // bytes = 110592

// Block tile 128x128, K-tile 64, 256 threads (8 warps, 4x2 grid, 32x64 each).
// cp.async 3-stage pipeline, single barrier per K-iter, ks-pipelined ldmatrix.
__device__ __forceinline__ void gemm_tile(
    const __nv_bfloat16* __restrict__ Ag, int lda,
    const __nv_bfloat16* __restrict__ Bg, int ldb,
    int K, float acc[2][8][4], __nv_bfloat16* smem)
{
    const int tid = threadIdx.x, lane = tid & 31, warp = tid >> 5;
    const int wm = warp & 3, wn = warp >> 2;
    const uint32_t sbase = smem_to_u32(smem);
    const int r0 = tid >> 3;            // staging row 0..31 (+32*rr)
    const int c0 = (tid & 7) << 3;      // staging col {0..56}
    const int nk = K / TK;

    // Per-lane ldmatrix base byte-offsets within a stage buffer.
    const uint32_t offA0 = (uint32_t)((wm * 32 + ((lane >> 3) & 1) * 8 + (lane & 7)) * SA
                                      + (lane >> 4) * 8) * 2;
    const uint32_t offA1 = offA0 + 16 * SA * 2;
    const uint32_t offB0 = (uint32_t)(STG + (wn * 64 + (lane >> 4) * 8 + (lane & 7)) * SA
                                      + ((lane >> 3) & 1) * 8) * 2;

    auto issue = [&](int i) {
        const int s = i % NS;
        const uint32_t sa = sbase + (uint32_t)(s * 2 * STG) * 2;
        const uint32_t sb = sa + STG * 2;
        const int k0 = i * TK;
        #pragma unroll
        for (int rr = 0; rr < 4; rr++) {
            const int row = rr * 32 + r0;
            cp16(sa + (row * SA + c0) * 2, Ag + (size_t)row * lda + k0 + c0);
            cp16(sb + (row * SA + c0) * 2, Bg + (size_t)row * ldb + k0 + c0);
        }
        CP_COMMIT();
    };

    auto ldfr = [&](uint32_t bb, int ks, uint32_t a[2][4], uint32_t b4[4][4]) {
        const uint32_t kofs = (uint32_t)ks * 32;   // 16 bf16 = 32 bytes
        ldsm4(a[0][0], a[0][1], a[0][2], a[0][3], bb + offA0 + kofs);
        ldsm4(a[1][0], a[1][1], a[1][2], a[1][3], bb + offA1 + kofs);
        #pragma unroll
        for (int jp = 0; jp < 4; jp++)
            ldsm4(b4[jp][0], b4[jp][1], b4[jp][2], b4[jp][3],
                  bb + offB0 + (uint32_t)(jp * 16 * SA * 2) + kofs);
    };

    // Prologue: fill up to NS-1 stages
    #pragma unroll
    for (int p = 0; p < NS - 1; p++)
        if (p < nk) issue(p);

    for (int i = 0; i < nk; i++) {
        if (i < nk - 1) CP_WAIT(1); else CP_WAIT(0);
        __syncthreads();                       // single barrier per iteration
        if (i + NS - 1 < nk) issue(i + NS - 1);

        const uint32_t bb = sbase + (uint32_t)((i % NS) * 2 * STG) * 2;
        uint32_t a[2][2][4], b4[2][4][4];
        ldfr(bb, 0, a[0], b4[0]);
        #pragma unroll
        for (int ks = 0; ks < 4; ks++) {       // four k16 steps per K-tile
            const int cur = ks & 1, nxt = cur ^ 1;
            if (ks < 3) ldfr(bb, ks + 1, a[nxt], b4[nxt]);
            #pragma unroll
            for (int ii = 0; ii < 2; ii++)
                #pragma unroll
                for (int jp = 0; jp < 4; jp++) {
                    mma_bf16(acc[ii][2 * jp],     a[cur][ii], b4[cur][jp][0], b4[cur][jp][1]);
                    mma_bf16(acc[ii][2 * jp + 1], a[cur][ii], b4[cur][jp][2], b4[cur][jp][3]);
                }
        }
    }
    __syncthreads();   // protect final buffers before caller reuses smem
}

// ---------------------------------------------------------------------------
// Prep kernels
// ---------------------------------------------------------------------------
__global__ void convert_x(const float* __restrict__ x) {
    size_t i = (size_t)blockIdx.x * 256 + threadIdx.x;
    float4 v = ((const float4*)x)[i];
    __nv_bfloat162 p0, p1;
    p0.x = __float2bfloat16(v.x); p0.y = __float2bfloat16(v.y);
    p1.x = __float2bfloat16(v.z); p1.y = __float2bfloat16(v.w);
    ((__nv_bfloat162*)g_Xb)[2 * i]     = p0;
    ((__nv_bfloat162*)g_Xb)[2 * i + 1] = p1;
}

__global__ void pack_w(const float* __restrict__ kf, const float* __restrict__ kg,
                       const float* __restrict__ kh) {
    int idx = blockIdx.x * 256 + threadIdx.x;
    int n = idx >> 9, k = idx & 511;
    float v;
    if (n < 64)       v = kf[k * 64 + n];
    else if (n < 128) v = kg[k * 64 + (n - 64)];
    else              v = kh[k * 512 + (n - 128)];
    g_Wt[idx] = __float2bfloat16(v);
}

__global__ void zero_l() {
    int i = blockIdx.x * 1024 + threadIdx.x;
    if (i < NROWS) g_l[i] = 0.f;
}

// ---------------------------------------------------------------------------
// GEMM 1: [f|g|v] = Xb @ W ; f/g -> g_FG, v -> g_V (natural, coalesced)
// ---------------------------------------------------------------------------
__global__ void __launch_bounds__(256, 2) gemm1_qkv() {
    extern __shared__ __nv_bfloat16 smem[];
    float acc[2][8][4];
    #pragma unroll
    for (int i = 0; i < 2; i++)
        #pragma unroll
        for (int j = 0; j < 8; j++)
            #pragma unroll
            for (int q = 0; q < 4; q++) acc[i][j][q] = 0.f;

    const int m0 = blockIdx.y * 128, n0 = blockIdx.x * 128;
    gemm_tile(g_Xb + (size_t)m0 * Cc, Cc, g_Wt + (size_t)n0 * Cc, Cc, Cc, acc, smem);

    const int lane = threadIdx.x & 31, warp = threadIdx.x >> 5;
    const int wm = warp & 3, wn = warp >> 2, g = lane >> 2, t4 = lane & 3;
    #pragma unroll
    for (int i = 0; i < 2; i++) {
        #pragma unroll
        for (int h = 0; h < 2; h++) {
            int r = m0 + wm * 32 + i * 16 + g + h * 8;
            #pragma unroll
            for (int j = 0; j < 8; j++) {
                int c = n0 + wn * 64 + j * 8 + 2 * t4;
                __nv_bfloat162 p;
                p.x = __float2bfloat16(acc[i][j][h * 2 + 0]);
                p.y = __float2bfloat16(acc[i][j][h * 2 + 1]);
                if (n0 == 0) *(__nv_bfloat162*)&g_FG[(size_t)r * 128 + c] = p;
                else         *(__nv_bfloat162*)&g_V [(size_t)r * Cc + (c - 128)] = p;
            }
        }
    }
}

// ---------------------------------------------------------------------------
// Transpose V [b][i][c] -> Vt [b][c][i] (smem tiled, coalesced both sides)
// ---------------------------------------------------------------------------
__global__ void vtrans() {
    __shared__ __nv_bfloat16 t[64 * 72];
    const int bb = blockIdx.z, it = blockIdx.x, ct = blockIdx.y;
    const __nv_bfloat16* src = g_V + ((size_t)bb * Np + it * 64) * Cc + ct * 64;
    #pragma unroll
    for (int k = 0; k < 2; k++) {
        int u = threadIdx.x + k * 256;
        int row = u >> 3, c8 = (u & 7) * 8;
        *(uint4*)(t + row * 72 + c8) = *(const uint4*)(src + (size_t)row * Cc + c8);
    }
    __syncthreads();
    __nv_bfloat16* dst = g_Vt + ((size_t)bb * Cc + ct * 64) * Np + it * 64;
    #pragma unroll
    for (int k = 0; k < 2; k++) {
        int u = threadIdx.x + k * 256;
        int orow = u >> 3, i8 = (u & 7) * 8;
        __nv_bfloat16 tmp[8];
        #pragma unroll
        for (int q = 0; q < 8; q++) tmp[q] = t[(i8 + q) * 72 + orow];
        *(uint4*)(dst + (size_t)orow * Np + i8) = *(uint4*)tmp;
    }
}

// ---------------------------------------------------------------------------
// GEMM 2: P = exp(F @ G^T) per batch, + fused row-sum atomics
// ---------------------------------------------------------------------------
__global__ void __launch_bounds__(256, 2) gemm2_score() {
    extern __shared__ __nv_bfloat16 smem[];
    float acc[2][8][4];
    #pragma unroll
    for (int i = 0; i < 2; i++)
        #pragma unroll
        for (int j = 0; j < 8; j++)
            #pragma unroll
            for (int q = 0; q < 4; q++) acc[i][j][q] = 0.f;

    const int n0 = blockIdx.x * 128, m0 = blockIdx.y * 128, bb = blockIdx.z;
    const __nv_bfloat16* A  = g_FG + ((size_t)bb * Np + m0) * 128;       // f
    const __nv_bfloat16* Bp = g_FG + ((size_t)bb * Np + n0) * 128 + 64;  // g
    gemm_tile(A, 128, Bp, 128, 64, acc, smem);

    __nv_bfloat16* Pb = g_P + (size_t)bb * Np * Np;
    const int lane = threadIdx.x & 31, warp = threadIdx.x >> 5;
    const int wm = warp & 3, wn = warp >> 2, g = lane >> 2, t4 = lane & 3;

    float rs[2][2] = {{0.f, 0.f}, {0.f, 0.f}};
    #pragma unroll
    for (int i = 0; i < 2; i++) {
        #pragma unroll
        for (int h = 0; h < 2; h++) {
            int r = m0 + wm * 32 + i * 16 + g + h * 8;
            #pragma unroll
            for (int j = 0; j < 8; j++) {
                int c = n0 + wn * 64 + j * 8 + 2 * t4;
                __nv_bfloat162 p;
                p.x = __float2bfloat16(__expf(acc[i][j][h * 2 + 0]));
                p.y = __float2bfloat16(__expf(acc[i][j][h * 2 + 1]));
                *(__nv_bfloat162*)&Pb[(size_t)r * Np + c] = p;
                rs[i][h] += __bfloat162float(p.x) + __bfloat162float(p.y);
            }
        }
    }
    #pragma unroll
    for (int i = 0; i < 2; i++) {
        #pragma unroll
        for (int h = 0; h < 2; h++) {
            float v = rs[i][h];
            v += __shfl_down_sync(0xffffffffu, v, 2, 4);
            v += __shfl_down_sync(0xffffffffu, v, 1, 4);
            if (t4 == 0) {
                int r = m0 + wm * 32 + i * 16 + g + h * 8;
                atomicAdd(&g_l[(size_t)bb * Np + r], v);
            }
        }
    }
}

// ---------------------------------------------------------------------------
// GEMM 3: out = gamma * (P @ Vt^T) / l + x   (per batch 4096x512, K=4096)
// ---------------------------------------------------------------------------
__global__ void __launch_bounds__(256, 2) gemm3_out(
    const float* __restrict__ x, const float* __restrict__ gamma,
    float* __restrict__ out)
{
    extern __shared__ __nv_bfloat16 smem[];
    float acc[2][8][4];
    #pragma unroll
    for (int i = 0; i < 2; i++)
        #pragma unroll
        for (int j = 0; j < 8; j++)
            #pragma unroll
            for (int q = 0; q < 4; q++) acc[i][j][q] = 0.f;

    const int n0 = blockIdx.x * 128, m0 = blockIdx.y * 128, bb = blockIdx.z;
    const __nv_bfloat16* A  = g_P  + ((size_t)bb * Np + m0) * Np;
    const __nv_bfloat16* Bp = g_Vt + ((size_t)bb * Cc + n0) * Np;
    gemm_tile(A, Np, Bp, Np, Np, acc, smem);

    const float gam = gamma[0];
    const int lane = threadIdx.x & 31, warp = threadIdx.x >> 5;
    const int wm = warp & 3, wn = warp >> 2, g = lane >> 2, t4 = lane & 3;

    #pragma unroll
    for (int i = 0; i < 2; i++) {
        #pragma unroll
        for (int h = 0; h < 2; h++) {
            int r = bb * Np + m0 + wm * 32 + i * 16 + g + h * 8;
            float inv = gam / g_l[r];
            #pragma unroll
            for (int j = 0; j < 8; j++) {
                int c = n0 + wn * 64 + j * 8 + 2 * t4;
                size_t o = (size_t)r * Cc + c;
                float2 xv = *(const float2*)(x + o);
                float2 ov;
                ov.x = acc[i][j][h * 2 + 0] * inv + xv.x;
                ov.y = acc[i][j][h * 2 + 1] * inv + xv.y;
                *(float2*)(out + o) = ov;
            }
        }
    }
}

// ===========================================================================
extern "C" void kernel_launch(void* const* d_in, const int* in_sizes, int n_in,
                              void* d_out, int out_size) {
    const float* x     = (const float*)d_in[0];
    const float* kf    = (const float*)d_in[1];
    const float* kg    = (const float*)d_in[2];
    const float* kh    = (const float*)d_in[3];
    const float* gamma = (const float*)d_in[4];
    float* out = (float*)d_out;

    static bool attr_done = false;
    if (!attr_done) {
        cudaFuncSetAttribute(gemm1_qkv,   cudaFuncAttributeMaxDynamicSharedMemorySize, GEMM_SMEM);
        cudaFuncSetAttribute(gemm2_score, cudaFuncAttributeMaxDynamicSharedMemorySize, GEMM_SMEM);
        cudaFuncSetAttribute(gemm3_out,   cudaFuncAttributeMaxDynamicSharedMemorySize, GEMM_SMEM);
        attr_done = true;
    }

    convert_x<<<(NROWS * Cc / 4) / 256, 256>>>(x);
    pack_w<<<(NW * Cc) / 256, 256>>>(kf, kg, kh);
    zero_l<<<16, 1024>>>();
    gemm1_qkv<<<dim3(NW / 128, NROWS / 128), 256, GEMM_SMEM>>>();
    vtrans<<<dim3(64, 8, 4), 256>>>();
    gemm2_score<<<dim3(Np / 128, Np / 128, Bn), 256, GEMM_SMEM>>>();
    gemm3_out<<<dim3(Cc / 128, Np / 128, Bn), 256, GEMM_SMEM>>>(x, gamma, out);
}